// round 12
// baseline (speedup 1.0000x reference)
#include <cuda_runtime.h>
#include <math.h>

// ---------------------------------------------------------------------------
// FIRE bias: out[h,s,t] = b2[h] + sum_w w2[h,w] * relu(w1[w]*nd(s,t) + b1[w])
// nd(s,t) = logrel[|s-t|] * invlognorm[s]  (two 1-D L1-resident tables)
// MLP is piecewise-affine in nd: bias_h = A[i][h]*nd + C[i][h] over <=W+1
// intervals (sorted breakpoints -b1/w1).
//
// Empirical law (R1..R9): table-driven hot loop = ~34us; MUFU-in-hot-loop
// variants = ~58us (MUFU throughput-bound). Keep tables.
// This round: PDL overlap of setup-exec with main-launch, with a guarded
// launch — if cudaLaunchKernelEx(+PDL) errors, fall back to a plain launch
// (cudaGridDependencySynchronize is a no-op for non-PDL launches).
// ---------------------------------------------------------------------------

#define FIRE_EPS 1e-6f
#define FIRE_LOG_BIAS 1.0f
#define MAX_S 4096
#define MAX_W 64
#define MAX_H 16

__device__ float g_logrel[MAX_S];
__device__ float g_invlognorm[MAX_S];
__device__ float g_sortedT[MAX_W];
__device__ float g_A[(MAX_W + 1) * MAX_H];
__device__ float g_C[(MAX_W + 1) * MAX_H];

// ---- setup kernel: blocks 0..NB-2 -> tables, last block -> coefficients --
__global__ void __launch_bounds__(512) fire_setup(
    const float* __restrict__ w1, const float* __restrict__ b1,
    const float* __restrict__ w2, const float* __restrict__ b2,
    const float* __restrict__ cp, const float* __restrict__ Lm,
    const float* __restrict__ iL, int S, int W, int H) {
    const int tid = threadIdx.x;
    const float c = __ldg(cp);

    if (blockIdx.x + 1 != gridDim.x) {
        // 1-D tables split across the leading blocks (1 entry/thread at S=2048)
        const float thr = fabsf(__ldg(Lm) * __ldg(iL));
        const int nb = gridDim.x - 1;
        for (int s = blockIdx.x * blockDim.x + tid; s < S; s += nb * blockDim.x) {
            float absrel = (float)s + FIRE_EPS;
            g_logrel[s] = logf(fmaf(absrel, c, FIRE_LOG_BIAS + FIRE_EPS));
            float posn = fmaxf((float)s, thr) + FIRE_EPS;
            g_invlognorm[s] = 1.0f / logf(fabsf(c * posn) + FIRE_LOG_BIAS + FIRE_EPS);
        }
        return;
    }

    // last block: breakpoints + per-interval coefficients
    __shared__ float s_t[MAX_W], s_sl[MAX_W], s_b1[MAX_W];
    __shared__ int s_rank[MAX_W];
    if (tid < W) {
        float sl = __ldg(w1 + tid);
        float bb = __ldg(b1 + tid);
        s_sl[tid] = sl;
        s_b1[tid] = bb;
        s_t[tid] = (sl != 0.0f) ? (-bb / sl) : __int_as_float(0x7f800000);
    }
    __syncthreads();
    if (tid < W) {  // rank sort, index tie-break
        float tw = s_t[tid];
        int r = 0;
        for (int v = 0; v < W; ++v) {
            float tv = s_t[v];
            if (tv < tw || (tv == tw && v < tid)) r++;
        }
        s_rank[tid] = r;
        g_sortedT[r] = tw;
    }
    __syncthreads();
    // interval i = #{sorted breakpoints < nd}; each (i,h) entry independent
    for (int k = tid; k < (W + 1) * H; k += blockDim.x) {
        int i = k / H;
        int h = k - i * H;
        float Asum = 0.0f;
        float Csum = __ldg(b2 + h);
        for (int w = 0; w < W; ++w) {
            float sl = s_sl[w];
            bool active;
            if (sl > 0.0f)      active = (i > s_rank[w]);
            else if (sl < 0.0f) active = (i <= s_rank[w]);
            else                active = (s_b1[w] > 0.0f);
            if (active) {
                float ww = __ldg(w2 + h * W + w);
                Asum = fmaf(ww, sl, Asum);
                Csum = fmaf(ww, s_b1[w], Csum);
            }
        }
        g_A[k] = Asum;
        g_C[k] = Csum;
    }
}

// ---- main streaming kernel (measured-best shape + PDL-safe wait) ---------
template <int H, int W>
__global__ void __launch_bounds__(256, 8) fire_main(float* __restrict__ out, int S) {
    __shared__ float shT[W];
    __shared__ float shA[(W + 1) * H];
    __shared__ float shC[(W + 1) * H];

    // PDL: wait for fire_setup's writes. No-op when launched without PDL.
    cudaGridDependencySynchronize();

    for (int k = threadIdx.x; k < W; k += blockDim.x) shT[k] = g_sortedT[k];
    for (int k = threadIdx.x; k < (W + 1) * H; k += blockDim.x) {
        shA[k] = g_A[k];
        shC[k] = g_C[k];
    }
    __syncthreads();

    const int s = blockIdx.y;
    const int t0 = (blockIdx.x * blockDim.x + threadIdx.x) * 4;
    if (t0 >= S) return;

    const float invln = __ldg(&g_invlognorm[s]);
    const size_t plane = (size_t)S * (size_t)S;
    const size_t rowbase = (size_t)s * (size_t)S;

    if (t0 + 3 < S) {
        float nd[4];
#pragma unroll
        for (int e = 0; e < 4; ++e) {
            int t = t0 + e;
            int d = (s >= t) ? (s - t) : (t - s);
            nd[e] = __ldg(&g_logrel[d]) * invln;
        }
        float ndmin = fminf(fminf(nd[0], nd[1]), fminf(nd[2], nd[3]));
        float ndmax = fmaxf(fmaxf(nd[0], nd[1]), fmaxf(nd[2], nd[3]));

        // lower_bound: i = #{shT[k] < v}
        int lo = 0, hi = W;
        while (lo < hi) { int m = (lo + hi) >> 1; if (shT[m] < ndmin) lo = m + 1; else hi = m; }
        int imin = lo;
        lo = imin; hi = W;
        while (lo < hi) { int m = (lo + hi) >> 1; if (shT[m] < ndmax) lo = m + 1; else hi = m; }
        int imax = lo;

        size_t base = rowbase + (size_t)t0;
        if (imin == imax) {
            int r = imin * H;
#pragma unroll
            for (int h = 0; h < H; ++h) {
                float a = shA[r + h];
                float cc = shC[r + h];
                float4 v;
                v.x = fmaf(a, nd[0], cc);
                v.y = fmaf(a, nd[1], cc);
                v.z = fmaf(a, nd[2], cc);
                v.w = fmaf(a, nd[3], cc);
                __stcs(reinterpret_cast<float4*>(out + (size_t)h * plane + base), v);
            }
        } else {
            int row[4];
#pragma unroll
            for (int e = 0; e < 4; ++e) {
                float v = nd[e];
                int l = imin, hh = imax;
                while (l < hh) { int m = (l + hh) >> 1; if (shT[m] < v) l = m + 1; else hh = m; }
                row[e] = l * H;
            }
#pragma unroll
            for (int h = 0; h < H; ++h) {
                float4 v;
                v.x = fmaf(shA[row[0] + h], nd[0], shC[row[0] + h]);
                v.y = fmaf(shA[row[1] + h], nd[1], shC[row[1] + h]);
                v.z = fmaf(shA[row[2] + h], nd[2], shC[row[2] + h]);
                v.w = fmaf(shA[row[3] + h], nd[3], shC[row[3] + h]);
                __stcs(reinterpret_cast<float4*>(out + (size_t)h * plane + base), v);
            }
        }
    } else {
        // scalar tail (unused when S % 4 == 0)
        for (int t = t0; t < S; ++t) {
            int d = (s >= t) ? (s - t) : (t - s);
            float v = __ldg(&g_logrel[d]) * invln;
            int lo = 0, hi = W;
            while (lo < hi) { int m = (lo + hi) >> 1; if (shT[m] < v) lo = m + 1; else hi = m; }
            for (int h = 0; h < H; ++h)
                out[(size_t)h * plane + rowbase + t] = fmaf(shA[lo * H + h], v, shC[lo * H + h]);
        }
    }
}

// ---- generic fallback (runtime H, W) -------------------------------------
__global__ void fire_generic(const float* __restrict__ w1, const float* __restrict__ b1,
                             const float* __restrict__ w2, const float* __restrict__ b2,
                             const float* __restrict__ cp, const float* __restrict__ Lm,
                             const float* __restrict__ iL,
                             float* __restrict__ out, int S, int W, int H) {
    int s = blockIdx.y;
    int t = blockIdx.x * blockDim.x + threadIdx.x;
    if (t >= S) return;
    float c = cp[0];
    float thr = fabsf(Lm[0] * iL[0]);
    int d = (s >= t) ? (s - t) : (t - s);
    float log_rel = logf(fmaf((float)d + FIRE_EPS, c, FIRE_LOG_BIAS + FIRE_EPS));
    float posn = fmaxf((float)s, thr) + FIRE_EPS;
    float nd = log_rel / logf(fabsf(c * posn) + FIRE_LOG_BIAS + FIRE_EPS);
    for (int h = 0; h < H; ++h) {
        float acc = b2[h];
        for (int w = 0; w < W; ++w) {
            float hv = fmaf(w1[w], nd, b1[w]);
            hv = fmaxf(hv, 0.0f);
            acc = fmaf(w2[h * W + w], hv, acc);
        }
        out[(size_t)h * S * S + (size_t)s * S + t] = acc;
    }
}

extern "C" void kernel_launch(void* const* d_in, const int* in_sizes, int n_in,
                              void* d_out, int out_size) {
    // inputs: x, w1, b1, w2, b2, c, L_multiplier, init_L  (x unused by the math)
    const float* w1 = (const float*)d_in[1];
    const float* b1 = (const float*)d_in[2];
    const float* w2 = (const float*)d_in[3];
    const float* b2 = (const float*)d_in[4];
    const float* c  = (const float*)d_in[5];
    const float* Lm = (const float*)d_in[6];
    const float* iL = (const float*)d_in[7];

    int W = in_sizes[1];          // w1 is (W,1)
    int H = in_sizes[4];          // b2 is (H,)
    long long ss = (long long)out_size / (long long)H;  // S*S
    int S = (int)(sqrt((double)ss) + 0.5);

    fire_setup<<<5, 512>>>(w1, b1, w2, b2, c, Lm, iL, S, W, H);

    if (H == 12 && W == 32) {
        dim3 grid((unsigned)((S + 1023) / 1024), (unsigned)S, 1);
        dim3 block(256, 1, 1);

        // Try PDL launch; on ANY error fall back to a plain launch so the
        // captured graph always contains a working main kernel.
        cudaLaunchConfig_t cfg = {};
        cfg.gridDim = grid;
        cfg.blockDim = block;
        cfg.dynamicSmemBytes = 0;
        cudaLaunchAttribute attr[1];
        attr[0].id = cudaLaunchAttributeProgrammaticStreamSerialization;
        attr[0].val.programmaticStreamSerializationAllowed = 1;
        cfg.attrs = attr;
        cfg.numAttrs = 1;
        cudaError_t e = cudaLaunchKernelEx(&cfg, fire_main<12, 32>, (float*)d_out, S);
        if (e != cudaSuccess) {
            (void)cudaGetLastError();  // clear sticky error state
            fire_main<12, 32><<<grid, block>>>((float*)d_out, S);
        }
    } else {
        dim3 block(256);
        dim3 grid((unsigned)((S + 255) / 256), (unsigned)S);
        fire_generic<<<grid, block>>>(w1, b1, w2, b2, c, Lm, iL, (float*)d_out, S, W, H);
    }
}